// round 17
// baseline (speedup 1.0000x reference)
#include <cuda_runtime.h>

#define T_STEPS 500
#define NB 4096
#define ROWS 28          // rows per CTA (with overlap; 148*28 >= 4096)
#define HR   14          // half rows
#define QR   7           // pass size (rows) — caps live accumulators
#define NCTA 148
#define NTHR 256

typedef unsigned long long ull;

// packed fp32x2 FMA (sm_103a FFMA2)
__device__ __forceinline__ ull ffma2(ull a, ull b, ull c) {
    ull d;
    asm("fma.rn.f32x2 %0, %1, %2, %3;" : "=l"(d) : "l"(a), "l"(b), "l"(c));
    return d;
}
__device__ __forceinline__ float pair_sum(ull p) {
    return __uint_as_float((unsigned)p) + __uint_as_float((unsigned)(p >> 32));
}
// named barrier: drift group (tids 0-127) id=1, diffusion group id=2
__device__ __forceinline__ void bar_group(int id) {
    asm volatile("bar.sync %0, %1;" :: "r"(id), "r"(128) : "memory");
}

// SMEM (floats only now — W1 lives in registers):
//   hsm[2][28][132], pp[2][4][28][40], ys[28][32], b2s[64]
//   (132 / 40 padding => all GEMM2 accesses single-phase; see R12)
#define HS   132
#define PPS  40
#define HSM_F  (2*ROWS*HS)                // 7392
#define PP_F   (2*4*ROWS*PPS)             // 8960
#define YS_F   (ROWS*32)                  // 896
#define SMEM_BYTES ((HSM_F + PP_F + YS_F + 64)*4)  // 69,248 B

__global__ __launch_bounds__(NTHR, 1)
void nsde13(const float* __restrict__ y0, const float* __restrict__ noise,
            const float* __restrict__ dw1, const float* __restrict__ db1,
            const float* __restrict__ dw2, const float* __restrict__ db2,
            const float* __restrict__ gw1, const float* __restrict__ gb1,
            const float* __restrict__ gw2, const float* __restrict__ gb2,
            float* __restrict__ out)
{
    extern __shared__ float smf[];
    float* hsm = smf;                 // [m][r][HS]
    float* pp  = hsm + HSM_F;         // [m][q][r][PPS]
    float* ys  = pp  + PP_F;          // [r][32]
    float* b2s = ys  + YS_F;          // [2][32]

    const int tid  = threadIdx.x;
    const int lane = tid & 31;
    const int wid  = tid >> 5;
    const int m    = wid >> 2;              // 0 drift, 1 diffusion
    // overlapping base: floor(bid*4068/147); full coverage, dup rows
    // recompute identical values (deterministic duplicate writes)
    const int base = (int)(((long long)blockIdx.x * (NB - ROWS)) / (NCTA - 1));

    // GEMM1 role: j-half + r-half
    const int hj  = (wid >> 1) & 1;
    const int rb1 = (wid & 1) * HR;
    const int j0  = hj * 64 + lane;
    const int j1  = j0 + 32;

    // GEMM2 role: j-quarter; lane -> outputs il, il+16; half-warp -> r-half
    const int q   = wid & 3;
    const int il  = lane & 15;
    const int rb2 = (lane >> 4) * HR;

    // ---- W1 rows j0, j1 -> registers (32 ull) ----
    const float* W1 = m ? gw1 : dw1;
    ull w1a[16], w1b[16];
    #pragma unroll
    for (int t = 0; t < 8; t++) {
        double2 v0 = *(const double2*)(W1 + j0 * 32 + t * 4);
        w1a[2*t]   = __double_as_longlong(v0.x);
        w1a[2*t+1] = __double_as_longlong(v0.y);
        double2 v1 = *(const double2*)(W1 + j1 * 32 + t * 4);
        w1b[2*t]   = __double_as_longlong(v1.x);
        w1b[2*t+1] = __double_as_longlong(v1.y);
    }
    // ---- W2 rows (i = il, il+16) for this quarter -> registers (32 ull) ----
    const float* W2 = m ? gw2 : dw2;
    ull w2p0[16], w2p1[16];
    #pragma unroll
    for (int t = 0; t < 8; t++) {
        double2 u0 = *(const double2*)(W2 + il * 128 + q * 32 + t * 4);
        w2p0[2*t]   = __double_as_longlong(u0.x);
        w2p0[2*t+1] = __double_as_longlong(u0.y);
        double2 u1 = *(const double2*)(W2 + (il + 16) * 128 + q * 32 + t * 4);
        w2p1[2*t]   = __double_as_longlong(u1.x);
        w2p1[2*t+1] = __double_as_longlong(u1.y);
    }
    const float* B1 = m ? gb1 : db1;
    const float b1_0 = B1[j0], b1_1 = B1[j1];
    if (tid < 64) b2s[tid] = (tid < 32) ? db2[tid] : gb2[tid - 32];

    // ---- init ys + out[0] (threads 0..223, one float4 each) ----
    if (tid < ROWS * 8) {
        int v4 = tid * 4;
        float4 val = *(const float4*)(y0 + (size_t)base * 32 + v4);
        *(float4*)(ys + v4) = val;
        *(float4*)(out + (size_t)base * 32 + v4) = val;
    }
    __syncthreads();

    const float dt   = 0.01f;
    const float sqdt = __fsqrt_rn(dt);
    float*       hwb = hsm + m * (ROWS * HS);
    const float* hq  = hsm + m * (ROWS * HS) + q * 32;
    float*       ppb = pp + (m * 4 + q) * (ROWS * PPS);

    for (int s = 0; s < T_STEPS; s++) {
        // prefetch step noise (float4, threads 0..223)
        float4 nv;
        if (tid < ROWS * 8)
            nv = *(const float4*)(noise + ((size_t)s * NB + base) * 32 + tid * 4);

        // ---- GEMM1: two passes of QR rows (caps live accums at 14 ull) ----
        #pragma unroll
        for (int p = 0; p < 2; p++) {
            const int r0 = rb1 + p * QR;
            ull acc0[QR], acc1[QR];
            const ull bi0 = (ull)__float_as_uint(b1_0);
            const ull bi1 = (ull)__float_as_uint(b1_1);
            #pragma unroll
            for (int r = 0; r < QR; r++) { acc0[r] = bi0; acc1[r] = bi1; }
            #pragma unroll
            for (int k4 = 0; k4 < 8; k4++) {
                #pragma unroll
                for (int r = 0; r < QR; r++) {
                    double2 yv = *(const double2*)(ys + (r0 + r) * 32 + k4 * 4);
                    ull ylo = __double_as_longlong(yv.x);
                    ull yhi = __double_as_longlong(yv.y);
                    acc0[r] = ffma2(w1a[2*k4],   ylo, acc0[r]);
                    acc0[r] = ffma2(w1a[2*k4+1], yhi, acc0[r]);
                    acc1[r] = ffma2(w1b[2*k4],   ylo, acc1[r]);
                    acc1[r] = ffma2(w1b[2*k4+1], yhi, acc1[r]);
                }
            }
            #pragma unroll
            for (int r = 0; r < QR; r++) {
                hwb[(r0 + r) * HS + j0] = fmaxf(pair_sum(acc0[r]), 0.0f);
                hwb[(r0 + r) * HS + j1] = fmaxf(pair_sum(acc1[r]), 0.0f);
            }
        }
        // h[m] produced and consumed entirely within group m
        bar_group(1 + m);

        // ---- GEMM2: two passes of QR rows; 1 h-load -> 4 ffma2 ----
        #pragma unroll
        for (int p = 0; p < 2; p++) {
            const int r0 = rb2 + p * QR;
            ull a0[QR], a1[QR];
            #pragma unroll
            for (int r = 0; r < QR; r++) { a0[r] = 0ull; a1[r] = 0ull; }
            const float* hrow = hq + r0 * HS;
            #pragma unroll
            for (int j4 = 0; j4 < 8; j4++) {
                #pragma unroll
                for (int r = 0; r < QR; r++) {
                    double2 hv = *(const double2*)(hrow + r * HS + j4 * 4);
                    ull hlo = __double_as_longlong(hv.x);
                    ull hhi = __double_as_longlong(hv.y);
                    a0[r] = ffma2(w2p0[2*j4],   hlo, a0[r]);
                    a0[r] = ffma2(w2p0[2*j4+1], hhi, a0[r]);
                    a1[r] = ffma2(w2p1[2*j4],   hlo, a1[r]);
                    a1[r] = ffma2(w2p1[2*j4+1], hhi, a1[r]);
                }
            }
            #pragma unroll
            for (int r = 0; r < QR; r++) {
                ppb[(r0 + r) * PPS + il]      = pair_sum(a0[r]);
                ppb[(r0 + r) * PPS + il + 16] = pair_sum(a1[r]);
            }
        }
        __syncthreads();

        // ---- reduce quarters + Euler–Maruyama: threads 0..223, float4 each ----
        if (tid < ROWS * 8) {
            int v4 = tid * 4;
            int r = v4 >> 5, i = v4 & 31;
            const float* p = pp + r * PPS + i;
            float4 pa = *(const float4*)(p);
            float4 pb = *(const float4*)(p + ROWS*PPS);
            float4 pc = *(const float4*)(p + 2*ROWS*PPS);
            float4 pd = *(const float4*)(p + 3*ROWS*PPS);
            float4 bv = *(const float4*)(b2s + i);
            float fx = pa.x + pb.x + pc.x + pd.x + bv.x;
            float fy = pa.y + pb.y + pc.y + pd.y + bv.y;
            float fz = pa.z + pb.z + pc.z + pd.z + bv.z;
            float fw = pa.w + pb.w + pc.w + pd.w + bv.w;
            const float* pg = p + 4*ROWS*PPS;
            float4 ga = *(const float4*)(pg);
            float4 gb = *(const float4*)(pg + ROWS*PPS);
            float4 gc = *(const float4*)(pg + 2*ROWS*PPS);
            float4 gd = *(const float4*)(pg + 3*ROWS*PPS);
            float4 bg = *(const float4*)(b2s + 32 + i);
            float gx = ga.x + gb.x + gc.x + gd.x + bg.x;
            float gy = ga.y + gb.y + gc.y + gd.y + bg.y;
            float gz = ga.z + gb.z + gc.z + gd.z + bg.z;
            float gw = ga.w + gb.w + gc.w + gd.w + bg.w;
            float4 yv = *(const float4*)(ys + v4);
            float4 z;
            z.x = fmaf(gx, sqdt * nv.x, fmaf(fx, dt, yv.x));
            z.y = fmaf(gy, sqdt * nv.y, fmaf(fy, dt, yv.y));
            z.z = fmaf(gz, sqdt * nv.z, fmaf(fz, dt, yv.z));
            z.w = fmaf(gw, sqdt * nv.w, fmaf(fw, dt, yv.w));
            *(float4*)(out + ((size_t)(s + 1) * NB + base) * 32 + v4) = z;
            *(float4*)(ys + v4) = z;   // rewrites exactly what it read
        }
        __syncthreads();
    }
}

extern "C" void kernel_launch(void* const* d_in, const int* in_sizes, int n_in,
                              void* d_out, int out_size)
{
    // metadata order: ts, y0, noise, drift_w1, drift_b1, drift_w2, drift_b2,
    //                 diff_w1, diff_b1, diff_w2, diff_b2
    const float* y0    = (const float*)d_in[1];
    const float* noise = (const float*)d_in[2];
    const float* dw1   = (const float*)d_in[3];
    const float* db1   = (const float*)d_in[4];
    const float* dw2   = (const float*)d_in[5];
    const float* db2   = (const float*)d_in[6];
    const float* gw1   = (const float*)d_in[7];
    const float* gb1   = (const float*)d_in[8];
    const float* gw2   = (const float*)d_in[9];
    const float* gb2   = (const float*)d_in[10];
    float* out = (float*)d_out;

    cudaFuncSetAttribute(nsde13,
                         cudaFuncAttributeMaxDynamicSharedMemorySize,
                         SMEM_BYTES);
    nsde13<<<NCTA, NTHR, SMEM_BYTES>>>(y0, noise, dw1, db1, dw2, db2,
                                       gw1, gb1, gw2, gb2, out);
}